// round 3
// baseline (speedup 1.0000x reference)
#include <cuda_runtime.h>
#include <math.h>

#define BB 8
#define NN 2048
#define CC 768
#define HH 12
#define MM 1536
#define RR 512
#define NSRC 1024
#define NDST 1024
#define C3 2304

// ---------------- scratch (static device globals; no allocations) ----------------
__device__ float g_metric[(size_t)BB * NN * CC];   // x / ||x||  (normalize-then-dot, matching ref order)
__device__ float g_nodemax[BB * NSRC];
__device__ int   g_nodeidx[BB * NSRC];
__device__ int   g_srcidx[BB * RR];
__device__ int   g_dstidx[BB * RR];
__device__ int   g_unmidx[BB * RR];
__device__ int   g_gather[BB * NSRC];
__device__ float g_counts[BB * NDST];
__device__ float g_xm[(size_t)BB * MM * CC];
__device__ float g_qkv[(size_t)BB * MM * C3];
__device__ float g_attn[(size_t)BB * MM * CC];
__device__ float g_y[(size_t)BB * MM * CC];

// ---------------- 1. normalized metric ----------------
__global__ void metric_k(const float* __restrict__ x) {
    int row = blockIdx.x;                  // 0..B*N-1
    const float* p = x + (size_t)row * CC;
    float* q = g_metric + (size_t)row * CC;
    float s = 0.f;
    for (int c = threadIdx.x; c < CC; c += 256) { float v = p[c]; s += v * v; }
    __shared__ float red[256];
    red[threadIdx.x] = s; __syncthreads();
    for (int o = 128; o > 0; o >>= 1) {
        if (threadIdx.x < o) red[threadIdx.x] += red[threadIdx.x + o];
        __syncthreads();
    }
    float nrm = sqrtf(red[0]);
    for (int c = threadIdx.x; c < CC; c += 256)
        q[c] = p[c] / nrm;
}

// ---------------- 2. matching: scores GEMM with running row max/argmax ----------------
__global__ void match_k() {
    int b  = blockIdx.x >> 4;
    int st = blockIdx.x & 15;
    const float* mb = g_metric + (size_t)b * NN * CC;
    int tid = threadIdx.x;
    int tx = tid & 15, ty = tid >> 4;

    __shared__ float As[16][68];
    __shared__ float Bs[16][68];
    __shared__ float rmax[64];
    __shared__ int   ridx[64];

    if (tid < 64) { rmax[tid] = -INFINITY; ridx[tid] = 0; }
    __syncthreads();

    int lr  = tid >> 2;
    int lc4 = (tid & 3) * 4;

    for (int dt = 0; dt < 16; dt++) {
        float acc[4][4] = {};
        for (int kt = 0; kt < 48; kt++) {
            float4 av = *(const float4*)&mb[(size_t)(2 * (st * 64 + lr)) * CC + kt * 16 + lc4];
            float4 bv = *(const float4*)&mb[(size_t)(2 * (dt * 64 + lr) + 1) * CC + kt * 16 + lc4];
            As[lc4 + 0][lr] = av.x; As[lc4 + 1][lr] = av.y;
            As[lc4 + 2][lr] = av.z; As[lc4 + 3][lr] = av.w;
            Bs[lc4 + 0][lr] = bv.x; Bs[lc4 + 1][lr] = bv.y;
            Bs[lc4 + 2][lr] = bv.z; Bs[lc4 + 3][lr] = bv.w;
            __syncthreads();
#pragma unroll
            for (int kk = 0; kk < 16; kk++) {
                float4 a4 = *(const float4*)&As[kk][ty * 4];
                float4 b4 = *(const float4*)&Bs[kk][tx * 4];
                float am[4] = {a4.x, a4.y, a4.z, a4.w};
                float bm[4] = {b4.x, b4.y, b4.z, b4.w};
#pragma unroll
                for (int i = 0; i < 4; i++)
#pragma unroll
                    for (int j = 0; j < 4; j++)
                        acc[i][j] += am[i] * bm[j];
            }
            __syncthreads();
        }
#pragma unroll
        for (int i = 0; i < 4; i++) {
            int r = ty * 4 + i;
            float bv = -INFINITY; int bi = 0;
#pragma unroll
            for (int j = 0; j < 4; j++) {
                int dg = dt * 64 + tx * 4 + j;
                float v = acc[i][j];
                if (v > bv) { bv = v; bi = dg; }
            }
            for (int off = 8; off; off >>= 1) {
                float ov = __shfl_xor_sync(0xffffffffu, bv, off);
                int   oi = __shfl_xor_sync(0xffffffffu, bi, off);
                if (ov > bv || (ov == bv && oi < bi)) { bv = ov; bi = oi; }
            }
            if (tx == 0) {
                if (bv > rmax[r] || (bv == rmax[r] && bi < ridx[r])) { rmax[r] = bv; ridx[r] = bi; }
            }
        }
    }
    // RACE-FREE write-out: the tx==0 owner thread of each row-group wrote
    // rmax[r]/ridx[r] itself for every dt — write its own rows directly.
    if (tx == 0) {
#pragma unroll
        for (int i = 0; i < 4; i++) {
            int r = (ty << 2) + i;
            g_nodemax[b * NSRC + st * 64 + r] = rmax[r];
            g_nodeidx[b * NSRC + st * 64 + r] = ridx[r];
        }
    }
}

// ---------------- 3. top-k + all index structures (1 block / batch) ----------------
__global__ void topk_k() {
    __shared__ unsigned long long key[1024];
    __shared__ int cnt[1024];
    __shared__ int mrg[1024];
    __shared__ int rnk[1024];
    int b = blockIdx.x, tid = threadIdx.x;   // 512 threads

    for (int i = tid; i < 1024; i += 512) {
        float v = g_nodemax[b * NSRC + i];
        unsigned u = __float_as_uint(v);
        u = (u & 0x80000000u) ? ~u : (u | 0x80000000u);
        key[i] = ((unsigned long long)(~u) << 32) | (unsigned)i;
        cnt[i] = 1; mrg[i] = 0;
    }
    __syncthreads();
    for (int k = 2; k <= 1024; k <<= 1)
        for (int j = k >> 1; j > 0; j >>= 1) {
            for (int i = tid; i < 1024; i += 512) {
                int ixj = i ^ j;
                if (ixj > i) {
                    bool up = ((i & k) == 0);
                    unsigned long long a = key[i], c2 = key[ixj];
                    if ((a > c2) == up) { key[i] = c2; key[ixj] = a; }
                }
            }
            __syncthreads();
        }
    {
        int s = (int)(key[tid] & 0xffffffffu);
        int d = g_nodeidx[b * NSRC + s];
        g_srcidx[b * RR + tid] = s;
        g_dstidx[b * RR + tid] = d;
        mrg[s] = 1;
        atomicAdd(&cnt[d], 1);
    }
    __syncthreads();
    if (tid == 0) {
        int run = 0;
        for (int s2 = 0; s2 < 1024; s2++) { rnk[s2] = run; if (!mrg[s2]) run++; }
    }
    __syncthreads();
    for (int i = tid; i < 1024; i += 512) {
        if (!mrg[i]) { g_unmidx[b * RR + rnk[i]] = i; g_gather[b * NSRC + i] = NDST + rnk[i]; }
        else         { g_gather[b * NSRC + i] = g_nodeidx[b * NSRC + i]; }
        g_counts[b * NDST + i] = (float)cnt[i];
    }
}

// ---------------- 4. build xm ----------------
__global__ void build_xm_k(const float* __restrict__ x) {
    int row = blockIdx.x;
    int b = row / MM, j = row - b * MM;
    const float* src;
    if (j < NDST) src = x + ((size_t)b * NN + 2 * j + 1) * CC;
    else { int s = g_unmidx[b * RR + (j - NDST)]; src = x + ((size_t)b * NN + 2 * s) * CC; }
    float* dst = g_xm + (size_t)row * CC;
    int t = threadIdx.x;                    // 192
    *(float4*)&dst[t * 4] = *(const float4*)&src[t * 4];
}

// ---------------- 5. merge: scatter-add ----------------
__global__ void merge_add_k(const float* __restrict__ x) {
    int b = blockIdx.x >> 9;
    int i = blockIdx.x & 511;
    int s = g_srcidx[b * RR + i];
    int d = g_dstidx[b * RR + i];
    const float* sp = x + ((size_t)b * NN + 2 * s) * CC;
    float* dp = g_xm + ((size_t)b * MM + d) * CC;
    int t = threadIdx.x;                    // 192
    float4 v = *(const float4*)&sp[t * 4];
    atomicAdd(&dp[t * 4 + 0], v.x);
    atomicAdd(&dp[t * 4 + 1], v.y);
    atomicAdd(&dp[t * 4 + 2], v.z);
    atomicAdd(&dp[t * 4 + 3], v.w);
}

// ---------------- 6. divide dst rows by counts ----------------
__global__ void divide_k() {
    int b = blockIdx.x >> 10;
    int d = blockIdx.x & 1023;
    float inv = 1.0f / g_counts[b * NDST + d];
    float* dp = g_xm + ((size_t)b * MM + d) * CC;
    int t = threadIdx.x;                    // 192
    float4 v = *(float4*)&dp[t * 4];
    v.x *= inv; v.y *= inv; v.z *= inv; v.w *= inv;
    *(float4*)&dp[t * 4] = v;
}

// ---------------- 7. SGEMM C = A*B + bias (row-major), 128x128x8, 8x8/thread ----------------
__global__ void sgemm_bias_k(const float* __restrict__ A, const float* __restrict__ Bm,
                             const float* __restrict__ bias, float* __restrict__ Cm,
                             int Md, int Nd, int Kd) {
    __shared__ float As[8][128];
    __shared__ float Bs[8][128];
    int tid = threadIdx.x;
    int tx = tid & 15, ty = tid >> 4;
    int bm = blockIdx.y * 128, bn = blockIdx.x * 128;
    float acc[8][8] = {};

    int arow = tid >> 1, ac = (tid & 1) * 4;
    int brow = tid >> 5, bc = (tid & 31) * 4;
    const float* Aptr = A + (size_t)(bm + arow) * Kd + ac;
    const float* Bptr = Bm + (size_t)brow * Nd + bn + bc;

    float4 av = *(const float4*)(Aptr);
    float4 bv = *(const float4*)(Bptr);
    for (int k0 = 0; k0 < Kd; k0 += 8) {
        As[ac + 0][arow] = av.x; As[ac + 1][arow] = av.y;
        As[ac + 2][arow] = av.z; As[ac + 3][arow] = av.w;
        *(float4*)&Bs[brow][bc] = bv;
        __syncthreads();
        if (k0 + 8 < Kd) {
            av = *(const float4*)(Aptr + k0 + 8);
            bv = *(const float4*)(Bptr + (size_t)(k0 + 8) * Nd);
        }
#pragma unroll
        for (int kk = 0; kk < 8; kk++) {
            float4 a0 = *(const float4*)&As[kk][ty * 8];
            float4 a1 = *(const float4*)&As[kk][ty * 8 + 4];
            float4 b0 = *(const float4*)&Bs[kk][tx * 8];
            float4 b1 = *(const float4*)&Bs[kk][tx * 8 + 4];
            float am[8] = {a0.x, a0.y, a0.z, a0.w, a1.x, a1.y, a1.z, a1.w};
            float bb[8] = {b0.x, b0.y, b0.z, b0.w, b1.x, b1.y, b1.z, b1.w};
#pragma unroll
            for (int i = 0; i < 8; i++)
#pragma unroll
                for (int j = 0; j < 8; j++)
                    acc[i][j] += am[i] * bb[j];
        }
        __syncthreads();
    }
#pragma unroll
    for (int i = 0; i < 8; i++) {
        size_t row = (size_t)(bm + ty * 8 + i);
        float* cp = Cm + row * Nd + bn + tx * 8;
        const float* bp = bias + bn + tx * 8;
        float4 o0 = {acc[i][0] + bp[0], acc[i][1] + bp[1], acc[i][2] + bp[2], acc[i][3] + bp[3]};
        float4 o1 = {acc[i][4] + bp[4], acc[i][5] + bp[5], acc[i][6] + bp[6], acc[i][7] + bp[7]};
        *(float4*)cp = o0;
        *(float4*)(cp + 4) = o1;
    }
}

// ---------------- 8. flash attention fp32, Br=Bc=64, online softmax ----------------
__global__ void flash_k(const float* __restrict__ qkv, float* __restrict__ o) {
    extern __shared__ float sm[];
    float* Qt   = sm;               // [d][r] 64x68
    float* KVs  = Qt + 64 * 68;     // Kt [d][c] / Vs [c][d]
    float* Pt   = KVs + 64 * 68;    // [c][r]
    float* mrow = Pt + 64 * 68;
    float* lrow = mrow + 64;

    int qt = blockIdx.x, bh = blockIdx.y;
    int b = bh / HH, h = bh % HH;
    const float* base = qkv + (size_t)b * MM * C3 + h * 64;
    int tid = threadIdx.x, tx = tid & 15, ty = tid >> 4;

    {
        int d = tid & 63, r0 = (tid >> 6) * 16;
        const float* qp = base + (size_t)(qt * 64) * C3 + d;
#pragma unroll
        for (int i = 0; i < 16; i++)
            Qt[d * 68 + r0 + i] = qp[(size_t)(r0 + i) * C3];
    }
    if (tid < 64) { mrow[tid] = -INFINITY; lrow[tid] = 0.f; }
    float acc[4][4] = {};
    const float scale = 0.125f;

    for (int kt = 0; kt < 24; kt++) {
        __syncthreads();
        {
            int d = tid & 63, c0 = (tid >> 6) * 16;
            const float* kp = base + CC + (size_t)(kt * 64) * C3 + d;
#pragma unroll
            for (int i = 0; i < 16; i++)
                KVs[d * 68 + c0 + i] = kp[(size_t)(c0 + i) * C3];
        }
        __syncthreads();

        float s_[4][4] = {};
#pragma unroll 8
        for (int d = 0; d < 64; d++) {
            float4 a4 = *(const float4*)&Qt[d * 68 + (ty << 2)];
            float4 b4 = *(const float4*)&KVs[d * 68 + (tx << 2)];
            float am[4] = {a4.x, a4.y, a4.z, a4.w};
            float bm[4] = {b4.x, b4.y, b4.z, b4.w};
#pragma unroll
            for (int i = 0; i < 4; i++)
#pragma unroll
                for (int j = 0; j < 4; j++)
                    s_[i][j] += am[i] * bm[j];
        }
#pragma unroll
        for (int i = 0; i < 4; i++)
#pragma unroll
            for (int j = 0; j < 4; j++)
                s_[i][j] *= scale;

        float mnewv[4], alphav[4], rsum[4];
#pragma unroll
        for (int i = 0; i < 4; i++) {
            float mloc = fmaxf(fmaxf(s_[i][0], s_[i][1]), fmaxf(s_[i][2], s_[i][3]));
            for (int off = 8; off; off >>= 1)
                mloc = fmaxf(mloc, __shfl_xor_sync(0xffffffffu, mloc, off));
            float mold = mrow[(ty << 2) + i];
            float mnew = fmaxf(mold, mloc);
            mnewv[i] = mnew;
            alphav[i] = __expf(mold - mnew);
            rsum[i] = 0.f;
        }
#pragma unroll
        for (int j = 0; j < 4; j++) {
            float4 pv;
            pv.x = __expf(s_[0][j] - mnewv[0]); rsum[0] += pv.x;
            pv.y = __expf(s_[1][j] - mnewv[1]); rsum[1] += pv.y;
            pv.z = __expf(s_[2][j] - mnewv[2]); rsum[2] += pv.z;
            pv.w = __expf(s_[3][j] - mnewv[3]); rsum[3] += pv.w;
            *(float4*)&Pt[(tx * 4 + j) * 68 + (ty << 2)] = pv;
        }
#pragma unroll
        for (int i = 0; i < 4; i++) {
            float r_ = rsum[i];
            for (int off = 8; off; off >>= 1)
                r_ += __shfl_xor_sync(0xffffffffu, r_, off);
            if (tx == 0) {
                int r = (ty << 2) + i;
                mrow[r] = mnewv[i];
                lrow[r] = lrow[r] * alphav[i] + r_;
            }
            acc[i][0] *= alphav[i]; acc[i][1] *= alphav[i];
            acc[i][2] *= alphav[i]; acc[i][3] *= alphav[i];
        }
        __syncthreads();
        {
            const float* vp = base + 2 * CC + (size_t)(kt * 64) * C3;
#pragma unroll
            for (int it = 0; it < 4; it++) {
                int idx = tid + it * 256;
                int r = idx >> 4, c4 = (idx & 15) << 2;
                *(float4*)&KVs[r * 68 + c4] = *(const float4*)&vp[(size_t)r * C3 + c4];
            }
        }
        __syncthreads();
#pragma unroll 4
        for (int c = 0; c < 64; c++) {
            float4 p4 = *(const float4*)&Pt[c * 68 + (ty << 2)];
            float4 v4 = *(const float4*)&KVs[c * 68 + (tx << 2)];
            float pm[4] = {p4.x, p4.y, p4.z, p4.w};
            float vm[4] = {v4.x, v4.y, v4.z, v4.w};
#pragma unroll
            for (int i = 0; i < 4; i++)
#pragma unroll
                for (int j = 0; j < 4; j++)
                    acc[i][j] += pm[i] * vm[j];
        }
    }
    __syncthreads();
#pragma unroll
    for (int i = 0; i < 4; i++) {
        float inv = 1.0f / lrow[(ty << 2) + i];
        size_t row = (size_t)b * MM + qt * 64 + (ty << 2) + i;
        float4 ov = {acc[i][0] * inv, acc[i][1] * inv, acc[i][2] * inv, acc[i][3] * inv};
        *(float4*)&o[row * CC + h * 64 + (tx << 2)] = ov;
    }
}

// ---------------- 9. unmerge: pure gather ----------------
__global__ void unmerge_k(float* __restrict__ out) {
    int row = blockIdx.x;
    int b = row >> 11;
    int n = row & 2047;
    int yrow = (n & 1) ? (n >> 1) : g_gather[b * NSRC + (n >> 1)];
    const float* src = g_y + ((size_t)b * MM + yrow) * CC;
    float* dst = out + (size_t)row * CC;
    int t = threadIdx.x;                  // 192
    *(float4*)&dst[t * 4] = *(const float4*)&src[t * 4];
}

// ---------------- launcher ----------------
extern "C" void kernel_launch(void* const* d_in, const int* in_sizes, int n_in,
                              void* d_out, int out_size) {
    const float* x    = (const float*)d_in[0];
    const float* Wqkv = (const float*)d_in[1];
    const float* bqkv = (const float*)d_in[2];
    const float* Wo   = (const float*)d_in[3];
    const float* bo   = (const float*)d_in[4];
    float* out = (float*)d_out;

    float *xm, *qkvb, *attnb, *yb;
    cudaGetSymbolAddress((void**)&xm, g_xm);
    cudaGetSymbolAddress((void**)&qkvb, g_qkv);
    cudaGetSymbolAddress((void**)&attnb, g_attn);
    cudaGetSymbolAddress((void**)&yb, g_y);

    cudaFuncSetAttribute(flash_k, cudaFuncAttributeMaxDynamicSharedMemorySize, 53248);

    metric_k<<<BB * NN, 256>>>(x);
    match_k<<<BB * 16, 256>>>();
    topk_k<<<BB, 512>>>();
    build_xm_k<<<BB * MM, 192>>>(x);
    merge_add_k<<<BB * RR, 192>>>(x);
    divide_k<<<BB * NDST, 192>>>();
    sgemm_bias_k<<<dim3(C3 / 128, (BB * MM) / 128), 256>>>(xm, Wqkv, bqkv, qkvb, BB * MM, C3, CC);
    flash_k<<<dim3(MM / 64, BB * HH), 256, 52736>>>(qkvb, attnb);
    sgemm_bias_k<<<dim3(CC / 128, (BB * MM) / 128), 256>>>(attnb, Wo, bo, yb, BB * MM, CC, CC);
    unmerge_k<<<BB * NN, 192>>>(out);
}

// round 4
// speedup vs baseline: 2.4185x; 2.4185x over previous
#include <cuda_runtime.h>
#include <math.h>

#define BB 8
#define NN 2048
#define CC 768
#define HH 12
#define MM 1536
#define RR 512
#define NSRC 1024
#define NDST 1024
#define C3 2304

// fp32 -> tf32 round-to-nearest (tensor-core ingest rounding)
__device__ __forceinline__ float tf32r(float x) {
    unsigned r; asm("cvt.rna.tf32.f32 %0, %1;" : "=r"(r) : "f"(x));
    return __uint_as_float(r);
}
// m16n8k8 tf32 MMA, fp32 accumulate
__device__ __forceinline__ void mma8(float c[4], const unsigned a[4], const unsigned b[2]) {
    asm volatile("mma.sync.aligned.m16n8k8.row.col.f32.tf32.tf32.f32 "
        "{%0,%1,%2,%3}, {%4,%5,%6,%7}, {%8,%9}, {%0,%1,%2,%3};"
        : "+f"(c[0]), "+f"(c[1]), "+f"(c[2]), "+f"(c[3])
        : "r"(a[0]), "r"(a[1]), "r"(a[2]), "r"(a[3]), "r"(b[0]), "r"(b[1]));
}

// ---------------- scratch ----------------
__device__ float g_metric[(size_t)BB * NN * CC];
__device__ float g_pmax[BB * 8 * NSRC];
__device__ int   g_pidx[BB * 8 * NSRC];
__device__ float g_nodemax[BB * NSRC];
__device__ int   g_nodeidx[BB * NSRC];
__device__ int   g_srcidx[BB * RR];
__device__ int   g_dstidx[BB * RR];
__device__ int   g_unmidx[BB * RR];
__device__ int   g_gather[BB * NSRC];
__device__ float g_counts[BB * NDST];
__device__ float g_xm[(size_t)BB * MM * CC];
__device__ float g_qkv[(size_t)BB * MM * C3];
__device__ float g_attn[(size_t)BB * MM * CC];
__device__ float g_y[(size_t)BB * MM * CC];

// ---------------- 1. normalized metric (exact fp32, same as R3) ----------------
__global__ void metric_k(const float* __restrict__ x) {
    int row = blockIdx.x;
    const float* p = x + (size_t)row * CC;
    float* q = g_metric + (size_t)row * CC;
    float s = 0.f;
    for (int c = threadIdx.x; c < CC; c += 256) { float v = p[c]; s += v * v; }
    __shared__ float red[256];
    red[threadIdx.x] = s; __syncthreads();
    for (int o = 128; o > 0; o >>= 1) {
        if (threadIdx.x < o) red[threadIdx.x] += red[threadIdx.x + o];
        __syncthreads();
    }
    float nrm = sqrtf(red[0]);
    for (int c = threadIdx.x; c < CC; c += 256)
        q[c] = p[c] / nrm;
}

// ---------------- 2a. matching scores, 128x128 tile, fp32-exact, partial argmax ----------------
__global__ __launch_bounds__(256, 2) void match128_k() {
    __shared__ float As[8][132];
    __shared__ float Bs[8][132];
    int dt = blockIdx.x, st = blockIdx.y, b = blockIdx.z;
    const float* mb = g_metric + (size_t)b * NN * CC;
    int tid = threadIdx.x;
    int tx = tid & 15, ty = tid >> 4;
    int lm = tid & 127, kq = (tid >> 7) * 4;
    const float* arow = mb + (size_t)(2 * (st * 128 + lm)) * CC + kq;
    const float* brow = mb + (size_t)(2 * (dt * 128 + lm) + 1) * CC + kq;
    float acc[8][8] = {};

    for (int k0 = 0; k0 < CC; k0 += 8) {
        float4 av = *(const float4*)(arow + k0);
        float4 bv = *(const float4*)(brow + k0);
        As[kq + 0][lm] = av.x; As[kq + 1][lm] = av.y;
        As[kq + 2][lm] = av.z; As[kq + 3][lm] = av.w;
        Bs[kq + 0][lm] = bv.x; Bs[kq + 1][lm] = bv.y;
        Bs[kq + 2][lm] = bv.z; Bs[kq + 3][lm] = bv.w;
        __syncthreads();
#pragma unroll
        for (int kk = 0; kk < 8; kk++) {
            float4 a0 = *(const float4*)&As[kk][ty * 8];
            float4 a1 = *(const float4*)&As[kk][ty * 8 + 4];
            float4 b0 = *(const float4*)&Bs[kk][tx * 8];
            float4 b1 = *(const float4*)&Bs[kk][tx * 8 + 4];
            float am[8] = {a0.x, a0.y, a0.z, a0.w, a1.x, a1.y, a1.z, a1.w};
            float bm[8] = {b0.x, b0.y, b0.z, b0.w, b1.x, b1.y, b1.z, b1.w};
#pragma unroll
            for (int i = 0; i < 8; i++)
#pragma unroll
                for (int j = 0; j < 8; j++)
                    acc[i][j] += am[i] * bm[j];
        }
        __syncthreads();
    }
#pragma unroll
    for (int i = 0; i < 8; i++) {
        float bv = acc[i][0]; int bj = 0;
#pragma unroll
        for (int j = 1; j < 8; j++)
            if (acc[i][j] > bv) { bv = acc[i][j]; bj = j; }
        int bi = dt * 128 + tx * 8 + bj;
        for (int off = 8; off; off >>= 1) {
            float ov = __shfl_xor_sync(0xffffffffu, bv, off);
            int   oi = __shfl_xor_sync(0xffffffffu, bi, off);
            if (ov > bv || (ov == bv && oi < bi)) { bv = ov; bi = oi; }
        }
        if (tx == 0) {
            int r = st * 128 + ty * 8 + i;
            g_pmax[(b * 8 + dt) * NSRC + r] = bv;
            g_pidx[(b * 8 + dt) * NSRC + r] = bi;
        }
    }
}

// ---------------- 2b. merge the 8 dt-partials per row (first-occurrence tie) ----------------
__global__ void matchred_k() {
    int g = blockIdx.x * 256 + threadIdx.x;   // 0..8191
    int b = g >> 10, r = g & 1023;
    float bv = g_pmax[(b * 8) * NSRC + r];
    int   bi = g_pidx[(b * 8) * NSRC + r];
    for (int dt = 1; dt < 8; dt++) {
        float v = g_pmax[(b * 8 + dt) * NSRC + r];
        if (v > bv) { bv = v; bi = g_pidx[(b * 8 + dt) * NSRC + r]; }
    }
    g_nodemax[b * NSRC + r] = bv;
    g_nodeidx[b * NSRC + r] = bi;
}

// ---------------- 3. top-k + index structures (unchanged, verified) ----------------
__global__ void topk_k() {
    __shared__ unsigned long long key[1024];
    __shared__ int cnt[1024];
    __shared__ int mrg[1024];
    __shared__ int rnk[1024];
    int b = blockIdx.x, tid = threadIdx.x;   // 512 threads

    for (int i = tid; i < 1024; i += 512) {
        float v = g_nodemax[b * NSRC + i];
        unsigned u = __float_as_uint(v);
        u = (u & 0x80000000u) ? ~u : (u | 0x80000000u);
        key[i] = ((unsigned long long)(~u) << 32) | (unsigned)i;
        cnt[i] = 1; mrg[i] = 0;
    }
    __syncthreads();
    for (int k = 2; k <= 1024; k <<= 1)
        for (int j = k >> 1; j > 0; j >>= 1) {
            for (int i = tid; i < 1024; i += 512) {
                int ixj = i ^ j;
                if (ixj > i) {
                    bool up = ((i & k) == 0);
                    unsigned long long a = key[i], c2 = key[ixj];
                    if ((a > c2) == up) { key[i] = c2; key[ixj] = a; }
                }
            }
            __syncthreads();
        }
    {
        int s = (int)(key[tid] & 0xffffffffu);
        int d = g_nodeidx[b * NSRC + s];
        g_srcidx[b * RR + tid] = s;
        g_dstidx[b * RR + tid] = d;
        mrg[s] = 1;
        atomicAdd(&cnt[d], 1);
    }
    __syncthreads();
    if (tid == 0) {
        int run = 0;
        for (int s2 = 0; s2 < 1024; s2++) { rnk[s2] = run; if (!mrg[s2]) run++; }
    }
    __syncthreads();
    for (int i = tid; i < 1024; i += 512) {
        if (!mrg[i]) { g_unmidx[b * RR + rnk[i]] = i; g_gather[b * NSRC + i] = NDST + rnk[i]; }
        else         { g_gather[b * NSRC + i] = g_nodeidx[b * NSRC + i]; }
        g_counts[b * NDST + i] = (float)cnt[i];
    }
}

// ---------------- 4-6. merge build (unchanged) ----------------
__global__ void build_xm_k(const float* __restrict__ x) {
    int row = blockIdx.x;
    int b = row / MM, j = row - b * MM;
    const float* src;
    if (j < NDST) src = x + ((size_t)b * NN + 2 * j + 1) * CC;
    else { int s = g_unmidx[b * RR + (j - NDST)]; src = x + ((size_t)b * NN + 2 * s) * CC; }
    float* dst = g_xm + (size_t)row * CC;
    int t = threadIdx.x;                    // 192
    *(float4*)&dst[t * 4] = *(const float4*)&src[t * 4];
}

__global__ void merge_add_k(const float* __restrict__ x) {
    int b = blockIdx.x >> 9;
    int i = blockIdx.x & 511;
    int s = g_srcidx[b * RR + i];
    int d = g_dstidx[b * RR + i];
    const float* sp = x + ((size_t)b * NN + 2 * s) * CC;
    float* dp = g_xm + ((size_t)b * MM + d) * CC;
    int t = threadIdx.x;                    // 192
    float4 v = *(const float4*)&sp[t * 4];
    atomicAdd(&dp[t * 4 + 0], v.x);
    atomicAdd(&dp[t * 4 + 1], v.y);
    atomicAdd(&dp[t * 4 + 2], v.z);
    atomicAdd(&dp[t * 4 + 3], v.w);
}

__global__ void divide_k() {
    int b = blockIdx.x >> 10;
    int d = blockIdx.x & 1023;
    float inv = 1.0f / g_counts[b * NDST + d];
    float* dp = g_xm + ((size_t)b * MM + d) * CC;
    int t = threadIdx.x;                    // 192
    float4 v = *(float4*)&dp[t * 4];
    v.x *= inv; v.y *= inv; v.z *= inv; v.w *= inv;
    *(float4*)&dp[t * 4] = v;
}

// ---------------- 7. tf32 tensor-core GEMM: C = A*B + bias ----------------
// block 128x128, 8 warps (4m x 2n), warp tile 32x64, k-step 16
__global__ __launch_bounds__(256, 2) void gemm_tf32_k(
        const float* __restrict__ A, const float* __restrict__ Bm,
        const float* __restrict__ bias, float* __restrict__ Cm, int Nd, int Kd) {
    __shared__ float As[128 * 20];   // [m][k] pad 20
    __shared__ float Bs[128 * 20];   // [n][k] pad 20
    int tid = threadIdx.x;
    int w = tid >> 5, l = tid & 31;
    int wm = w & 3, wn = w >> 2;
    int lr = l >> 2, lc = l & 3;
    int bm = blockIdx.y * 128, bn = blockIdx.x * 128;
    float acc[2][8][4] = {};

    int ar = tid >> 2, ak = (tid & 3) * 4;
    int bnn = tid & 127, bk = (tid >> 7) * 8;
    const float* Ap0 = A + (size_t)(bm + ar) * Kd + ak;
    const float* Ap1 = A + (size_t)(bm + ar + 64) * Kd + ak;
    const float* Bp  = Bm + bn + bnn;

    float4 a0v = *(const float4*)Ap0;
    float4 a1v = *(const float4*)Ap1;
    float btmp[8];
#pragma unroll
    for (int j = 0; j < 8; j++) btmp[j] = Bp[(size_t)(bk + j) * Nd];

    for (int k0 = 0; k0 < Kd; k0 += 16) {
        *(float4*)&As[ar * 20 + ak] =
            make_float4(tf32r(a0v.x), tf32r(a0v.y), tf32r(a0v.z), tf32r(a0v.w));
        *(float4*)&As[(ar + 64) * 20 + ak] =
            make_float4(tf32r(a1v.x), tf32r(a1v.y), tf32r(a1v.z), tf32r(a1v.w));
        *(float4*)&Bs[bnn * 20 + bk] =
            make_float4(tf32r(btmp[0]), tf32r(btmp[1]), tf32r(btmp[2]), tf32r(btmp[3]));
        *(float4*)&Bs[bnn * 20 + bk + 4] =
            make_float4(tf32r(btmp[4]), tf32r(btmp[5]), tf32r(btmp[6]), tf32r(btmp[7]));
        __syncthreads();
        if (k0 + 16 < Kd) {
            a0v = *(const float4*)(Ap0 + k0 + 16);
            a1v = *(const float4*)(Ap1 + k0 + 16);
#pragma unroll
            for (int j = 0; j < 8; j++) btmp[j] = Bp[(size_t)(k0 + 16 + bk + j) * Nd];
        }
#pragma unroll
        for (int ks = 0; ks < 2; ks++) {
            int kc = ks * 8 + lc;
            unsigned af[2][4];
#pragma unroll
            for (int mt = 0; mt < 2; mt++) {
                int mr = wm * 32 + mt * 16 + lr;
                af[mt][0] = __float_as_uint(As[mr * 20 + kc]);
                af[mt][1] = __float_as_uint(As[(mr + 8) * 20 + kc]);
                af[mt][2] = __float_as_uint(As[mr * 20 + kc + 4]);
                af[mt][3] = __float_as_uint(As[(mr + 8) * 20 + kc + 4]);
            }
#pragma unroll
            for (int nt = 0; nt < 8; nt++) {
                int nc = wn * 64 + nt * 8 + lr;
                unsigned bf[2] = { __float_as_uint(Bs[nc * 20 + kc]),
                                   __float_as_uint(Bs[nc * 20 + kc + 4]) };
                mma8(acc[0][nt], af[0], bf);
                mma8(acc[1][nt], af[1], bf);
            }
        }
        __syncthreads();
    }
#pragma unroll
    for (int mt = 0; mt < 2; mt++) {
        int r0 = bm + wm * 32 + mt * 16 + lr;
#pragma unroll
        for (int nt = 0; nt < 8; nt++) {
            int c = bn + wn * 64 + nt * 8 + 2 * lc;
            float b0 = bias[c], b1 = bias[c + 1];
            *(float2*)&Cm[(size_t)r0 * Nd + c] =
                make_float2(acc[mt][nt][0] + b0, acc[mt][nt][1] + b1);
            *(float2*)&Cm[(size_t)(r0 + 8) * Nd + c] =
                make_float2(acc[mt][nt][2] + b0, acc[mt][nt][3] + b1);
        }
    }
}

// ---------------- 8. flash attention, tf32 MMA, Br=128 Bc=64, online softmax ----------------
__global__ __launch_bounds__(256, 2) void flash_tf32_k(
        const float* __restrict__ qkv, float* __restrict__ o) {
    extern __shared__ float sm[];
    float* Qs = sm;              // [128][68]  (m,k)
    float* Ks = Qs + 128 * 68;   // [64][68]   K as (n,k); reused as Vt (d,c)
    float* Ps = Ks + 64 * 68;    // [128][68]  P as (m,c)

    int qt = blockIdx.x, bh = blockIdx.y;
    int b = bh / HH, h = bh % HH;
    const float* base = qkv + (size_t)b * MM * C3 + h * 64;
    int tid = threadIdx.x;
    int w = tid >> 5, l = tid & 31;
    int lr = l >> 2, lc = l & 3;
    int mr0 = w * 16 + lr;       // warp's rows: mr0, mr0+8

    {   // load Q once (tf32)
        int r = tid >> 1, hf = (tid & 1) * 32;
        const float* qp = base + (size_t)(qt * 128 + r) * C3 + hf;
#pragma unroll
        for (int i = 0; i < 8; i++) {
            float4 v = *(const float4*)(qp + i * 4);
            *(float4*)&Qs[r * 68 + hf + i * 4] =
                make_float4(tf32r(v.x), tf32r(v.y), tf32r(v.z), tf32r(v.w));
        }
    }
    float om[8][4] = {};
    float m0 = -INFINITY, m1 = -INFINITY, l0 = 0.f, l1 = 0.f;

    for (int kt = 0; kt < 24; kt++) {
        __syncthreads();                    // prev Vt consumed / Q visible
        {   // load K tile (n,k)
            int r = tid >> 2, qq = (tid & 3) * 16;
            const float* kp = base + CC + (size_t)(kt * 64 + r) * C3 + qq;
#pragma unroll
            for (int i = 0; i < 4; i++) {
                float4 v = *(const float4*)(kp + i * 4);
                *(float4*)&Ks[r * 68 + qq + i * 4] =
                    make_float4(tf32r(v.x), tf32r(v.y), tf32r(v.z), tf32r(v.w));
            }
        }
        __syncthreads();
        // S = Q K^T
        float s[8][4] = {};
#pragma unroll
        for (int ks = 0; ks < 8; ks++) {
            int kb = ks * 8 + lc;
            unsigned af[4];
            af[0] = __float_as_uint(Qs[mr0 * 68 + kb]);
            af[1] = __float_as_uint(Qs[(mr0 + 8) * 68 + kb]);
            af[2] = __float_as_uint(Qs[mr0 * 68 + kb + 4]);
            af[3] = __float_as_uint(Qs[(mr0 + 8) * 68 + kb + 4]);
#pragma unroll
            for (int nt = 0; nt < 8; nt++) {
                int nc = nt * 8 + lr;
                unsigned bf[2] = { __float_as_uint(Ks[nc * 68 + kb]),
                                   __float_as_uint(Ks[nc * 68 + kb + 4]) };
                mma8(s[nt], af, bf);
            }
        }
        // online softmax
        float mx0 = -INFINITY, mx1 = -INFINITY;
#pragma unroll
        for (int nt = 0; nt < 8; nt++) {
            s[nt][0] *= 0.125f; s[nt][1] *= 0.125f;
            s[nt][2] *= 0.125f; s[nt][3] *= 0.125f;
            mx0 = fmaxf(mx0, fmaxf(s[nt][0], s[nt][1]));
            mx1 = fmaxf(mx1, fmaxf(s[nt][2], s[nt][3]));
        }
        mx0 = fmaxf(mx0, __shfl_xor_sync(0xffffffffu, mx0, 1));
        mx0 = fmaxf(mx0, __shfl_xor_sync(0xffffffffu, mx0, 2));
        mx1 = fmaxf(mx1, __shfl_xor_sync(0xffffffffu, mx1, 1));
        mx1 = fmaxf(mx1, __shfl_xor_sync(0xffffffffu, mx1, 2));
        float mn0 = fmaxf(m0, mx0), mn1 = fmaxf(m1, mx1);
        float al0 = __expf(m0 - mn0), al1 = __expf(m1 - mn1);
        m0 = mn0; m1 = mn1;
        float rs0 = 0.f, rs1 = 0.f;
#pragma unroll
        for (int nt = 0; nt < 8; nt++) {
            float p0 = __expf(s[nt][0] - mn0), p1 = __expf(s[nt][1] - mn0);
            float p2 = __expf(s[nt][2] - mn1), p3 = __expf(s[nt][3] - mn1);
            rs0 += p0 + p1; rs1 += p2 + p3;
            int c = nt * 8 + 2 * lc;
            *(float2*)&Ps[mr0 * 68 + c]       = make_float2(tf32r(p0), tf32r(p1));
            *(float2*)&Ps[(mr0 + 8) * 68 + c] = make_float2(tf32r(p2), tf32r(p3));
        }
        rs0 += __shfl_xor_sync(0xffffffffu, rs0, 1);
        rs0 += __shfl_xor_sync(0xffffffffu, rs0, 2);
        rs1 += __shfl_xor_sync(0xffffffffu, rs1, 1);
        rs1 += __shfl_xor_sync(0xffffffffu, rs1, 2);
        l0 = l0 * al0 + rs0; l1 = l1 * al1 + rs1;
#pragma unroll
        for (int nt = 0; nt < 8; nt++) {
            om[nt][0] *= al0; om[nt][1] *= al0;
            om[nt][2] *= al1; om[nt][3] *= al1;
        }
        __syncthreads();                    // Ks (K) fully consumed
        {   // load V transposed into Ks buffer: Vt[d][c]
            int d = tid & 63, cb = (tid >> 6) * 16;
            const float* vp = base + 2 * CC + (size_t)(kt * 64 + cb) * C3 + d;
#pragma unroll
            for (int i = 0; i < 16; i++)
                Ks[d * 68 + cb + i] = tf32r(vp[(size_t)i * C3]);
        }
        __syncthreads();
        // O += P V
#pragma unroll
        for (int ks = 0; ks < 8; ks++) {
            int kb = ks * 8 + lc;
            unsigned af[4];
            af[0] = __float_as_uint(Ps[mr0 * 68 + kb]);
            af[1] = __float_as_uint(Ps[(mr0 + 8) * 68 + kb]);
            af[2] = __float_as_uint(Ps[mr0 * 68 + kb + 4]);
            af[3] = __float_as_uint(Ps[(mr0 + 8) * 68 + kb + 4]);
#pragma unroll
            for (int nt = 0; nt < 8; nt++) {
                int nc = nt * 8 + lr;
                unsigned bf[2] = { __float_as_uint(Ks[nc * 68 + kb]),
                                   __float_as_uint(Ks[nc * 68 + kb + 4]) };
                mma8(om[nt], af, bf);
            }
        }
    }
    float i0 = 1.f / l0, i1 = 1.f / l1;
    size_t row0 = (size_t)b * MM + qt * 128 + mr0;
#pragma unroll
    for (int nt = 0; nt < 8; nt++) {
        int c = h * 64 + nt * 8 + 2 * lc;
        *(float2*)&o[row0 * CC + c]       = make_float2(om[nt][0] * i0, om[nt][1] * i0);
        *(float2*)&o[(row0 + 8) * CC + c] = make_float2(om[nt][2] * i1, om[nt][3] * i1);
    }
}

// ---------------- 9. unmerge (unchanged) ----------------
__global__ void unmerge_k(float* __restrict__ out) {
    int row = blockIdx.x;
    int b = row >> 11;
    int n = row & 2047;
    int yrow = (n & 1) ? (n >> 1) : g_gather[b * NSRC + (n >> 1)];
    const float* src = g_y + ((size_t)b * MM + yrow) * CC;
    float* dst = out + (size_t)row * CC;
    int t = threadIdx.x;                  // 192
    *(float4*)&dst[t * 4] = *(const float4*)&src[t * 4];
}

// ---------------- launcher ----------------
extern "C" void kernel_launch(void* const* d_in, const int* in_sizes, int n_in,
                              void* d_out, int out_size) {
    const float* x    = (const float*)d_in[0];
    const float* Wqkv = (const float*)d_in[1];
    const float* bqkv = (const float*)d_in[2];
    const float* Wo   = (const float*)d_in[3];
    const float* bo   = (const float*)d_in[4];
    float* out = (float*)d_out;

    float *xm, *qkvb, *attnb, *yb;
    cudaGetSymbolAddress((void**)&xm, g_xm);
    cudaGetSymbolAddress((void**)&qkvb, g_qkv);
    cudaGetSymbolAddress((void**)&attnb, g_attn);
    cudaGetSymbolAddress((void**)&yb, g_y);

    cudaFuncSetAttribute(flash_tf32_k, cudaFuncAttributeMaxDynamicSharedMemorySize, 87040);

    metric_k<<<BB * NN, 256>>>(x);
    match128_k<<<dim3(8, 8, 8), 256>>>();
    matchred_k<<<32, 256>>>();
    topk_k<<<BB, 512>>>();
    build_xm_k<<<BB * MM, 192>>>(x);
    merge_add_k<<<BB * RR, 192>>>(x);
    divide_k<<<BB * NDST, 192>>>();
    gemm_tf32_k<<<dim3(C3 / 128, (BB * MM) / 128), 256>>>(xm, Wqkv, bqkv, qkvb, C3, CC);
    flash_tf32_k<<<dim3(MM / 128, BB * HH), 256, 87040>>>(qkvb, attnb);
    gemm_tf32_k<<<dim3(CC / 128, (BB * MM) / 128), 256>>>(attnb, Wo, bo, yb, CC, CC);
    unmerge_k<<<BB * NN, 192>>>(out);
}